// round 2
// baseline (speedup 1.0000x reference)
#include <cuda_runtime.h>
#include <math.h>

#define B_     4
#define S_     4096
#define D_     1024
#define GRP    256
#define HEAD_  128
#define INNER_ 2048
#define G_     16
#define NCHUNK (B_*G_)      // 64
#define BS_    (B_*S_)      // 16384

// ---------------- scratch (no cudaMalloc allowed) ----------------
__device__ float g_v   [(size_t)BS_*INNER_];   // silu(x@Wv+bv)
__device__ float g_gate[(size_t)BS_*INNER_];   // silu(x@Wg+bg)
__device__ float g_vq  [(size_t)BS_*INNER_];   // v_quad
__device__ float g_om  [(size_t)BS_*INNER_];   // (v_quad+v_lin)*gate
__device__ float g_xh  [(size_t)BS_*HEAD_];    // silu(x@Win+bin)
__device__ float g_qq  [(size_t)BS_*HEAD_];
__device__ float g_qk  [(size_t)BS_*HEAD_];
__device__ float g_lq  [(size_t)BS_*HEAD_];
__device__ float g_lk  [(size_t)BS_*HEAD_];
__device__ float g_attn[(size_t)NCHUNK*GRP*GRP];
__device__ float g_kv  [(size_t)NCHUNK*HEAD_*INNER_];

// ---------------- generic SGEMM: 128x128 block, 8x8 per-thread ----------------
// C[M,N] = A @ B (+ epilogue). TA=true reads A as [K,M] (i.e. computes A^T@B).
// Batched via blockIdx.z with element strides sA/sB/sC.
#define EPI_NONE 0
#define EPI_SILU 1
#define EPI_BIAS 2
#define EPI_VQG  3

template<bool TA, int EPI>
__global__ void __launch_bounds__(256)
sgemm_k(const float* __restrict__ A, const float* __restrict__ B,
        float* __restrict__ C, int M, int N, int K,
        long long sA, long long sB, long long sC,
        const float* __restrict__ bias,
        const float* __restrict__ add,     // EPI_VQG: v_quad (stride sC)
        const float* __restrict__ gate)    // EPI_VQG: gate   (stride sC)
{
    __shared__ float As[8][128];
    __shared__ float Bs[8][128];

    const int bz = blockIdx.z;
    A += (long long)bz * sA;
    B += (long long)bz * sB;
    C += (long long)bz * sC;
    const float* addp  = (EPI == EPI_VQG) ? add  + (long long)bz * sC : nullptr;
    const float* gatep = (EPI == EPI_VQG) ? gate + (long long)bz * sC : nullptr;

    const int tid  = threadIdx.x;
    const int tx   = tid & 15;          // 0..15 -> N
    const int ty   = tid >> 4;          // 0..15 -> M
    const int row0 = blockIdx.y * 128;
    const int col0 = blockIdx.x * 128;

    // load indices
    const int arow = tid >> 1;          // 0..127   (non-TA A)
    const int acol = (tid & 1) * 4;     // 0 or 4
    const int brow = tid >> 5;          // 0..7     (B tile and TA A)
    const int bcol = (tid & 31) * 4;    // 0..124

    float acc[8][8];
#pragma unroll
    for (int i = 0; i < 8; i++)
#pragma unroll
        for (int j = 0; j < 8; j++) acc[i][j] = 0.f;

    for (int kt = 0; kt < K; kt += 8) {
        if (!TA) {
            float4 a = *(const float4*)&A[(long long)(row0 + arow) * K + kt + acol];
            As[acol + 0][arow] = a.x;
            As[acol + 1][arow] = a.y;
            As[acol + 2][arow] = a.z;
            As[acol + 3][arow] = a.w;
        } else {
            float4 a = *(const float4*)&A[(long long)(kt + brow) * M + row0 + bcol];
            *(float4*)&As[brow][bcol] = a;
        }
        float4 b = *(const float4*)&B[(long long)(kt + brow) * N + col0 + bcol];
        *(float4*)&Bs[brow][bcol] = b;
        __syncthreads();

#pragma unroll
        for (int k = 0; k < 8; k++) {
            float af[8], bf[8];
            *(float4*)&af[0] = *(const float4*)&As[k][ty * 8];
            *(float4*)&af[4] = *(const float4*)&As[k][ty * 8 + 4];
            *(float4*)&bf[0] = *(const float4*)&Bs[k][tx * 8];
            *(float4*)&bf[4] = *(const float4*)&Bs[k][tx * 8 + 4];
#pragma unroll
            for (int i = 0; i < 8; i++)
#pragma unroll
                for (int j = 0; j < 8; j++) acc[i][j] = fmaf(af[i], bf[j], acc[i][j]);
        }
        __syncthreads();
    }

#pragma unroll
    for (int i = 0; i < 8; i++) {
        const int r = row0 + ty * 8 + i;
#pragma unroll
        for (int j = 0; j < 8; j++) {
            const int c = col0 + tx * 8 + j;
            const long long idx = (long long)r * N + c;
            float val = acc[i][j];
            if (EPI == EPI_SILU) {
                float t = val + bias[c];
                val = t / (1.f + expf(-t));
            } else if (EPI == EPI_BIAS) {
                val += bias[c];
            } else if (EPI == EPI_VQG) {
                val = (val + addp[idx]) * gatep[idx];
            }
            C[idx] = val;
        }
    }
}

// ---------------- per-channel affine q/k generation ----------------
__global__ void affine_k(const float* __restrict__ xh,
                         const float* __restrict__ gqq, const float* __restrict__ bqq,
                         const float* __restrict__ gqk, const float* __restrict__ bqk,
                         const float* __restrict__ glq, const float* __restrict__ blq,
                         const float* __restrict__ glk, const float* __restrict__ blk,
                         float* __restrict__ qq, float* __restrict__ qk,
                         float* __restrict__ lq, float* __restrict__ lk)
{
    long long i = (long long)blockIdx.x * blockDim.x + threadIdx.x;
    if (i >= (long long)BS_ * HEAD_) return;
    int h = (int)(i & (HEAD_ - 1));
    float v = xh[i];
    qq[i] = fmaf(v, gqq[h], bqq[h]);
    qk[i] = fmaf(v, gqk[h], bqk[h]);
    lq[i] = fmaf(v, glq[h], blq[h]);
    lk[i] = fmaf(v, glk[h], blk[h]);
}

// ---------------- local quadratic attention scores ----------------
// attn[n,m] = relu( (qq[n]·qk[m]) / sqrt(2048), masked m<=n )^2   per chunk
__global__ void __launch_bounds__(256)
scores_k(const float* __restrict__ qq, const float* __restrict__ qk,
         float* __restrict__ attn)
{
    __shared__ float Qs[64][68];
    __shared__ float Ks[64][68];
    const int chunk = blockIdx.z;
    const int m0 = blockIdx.x * 64;      // key tile
    const int n0 = blockIdx.y * 64;      // query tile
    const float* q  = qq + (long long)chunk * GRP * HEAD_;
    const float* kp = qk + (long long)chunk * GRP * HEAD_;
    float* out = attn + (long long)chunk * GRP * GRP;

    const int tid = threadIdx.x;
    const int tx = tid & 15, ty = tid >> 4;

    float acc[4][4] = {};
    for (int kh = 0; kh < HEAD_; kh += 64) {
        for (int i = tid; i < 64 * 16; i += 256) {
            int r = i >> 4, c4 = (i & 15) * 4;
            *(float4*)&Qs[r][c4] = *(const float4*)&q [(long long)(n0 + r) * HEAD_ + kh + c4];
            *(float4*)&Ks[r][c4] = *(const float4*)&kp[(long long)(m0 + r) * HEAD_ + kh + c4];
        }
        __syncthreads();
#pragma unroll 8
        for (int k = 0; k < 64; k++) {
            float a[4], b[4];
#pragma unroll
            for (int i = 0; i < 4; i++) a[i] = Qs[ty * 4 + i][k];
#pragma unroll
            for (int j = 0; j < 4; j++) b[j] = Ks[tx * 4 + j][k];
#pragma unroll
            for (int i = 0; i < 4; i++)
#pragma unroll
                for (int j = 0; j < 4; j++) acc[i][j] = fmaf(a[i], b[j], acc[i][j]);
        }
        __syncthreads();
    }

    const float inv_scale = 1.0f / 45.25483399593904f;   // 1/sqrt(2048)
#pragma unroll
    for (int i = 0; i < 4; i++) {
        int n = n0 + ty * 4 + i;
#pragma unroll
        for (int j = 0; j < 4; j++) {
            int m = m0 + tx * 4 + j;
            float s = (m <= n) ? acc[i][j] * inv_scale : 0.f;
            s = fmaxf(s, 0.f);
            out[(long long)n * GRP + m] = s * s;
        }
    }
}

// ---------------- exclusive cumsum of kv over chunk axis ----------------
__global__ void cumsum_k(float* __restrict__ kv)
{
    const long long HE = (long long)HEAD_ * INNER_;      // 262144
    long long i = (long long)blockIdx.x * blockDim.x + threadIdx.x;
    if (i >= (long long)B_ * HE) return;
    long long b  = i / HE;
    long long he = i - b * HE;
    float* p = kv + b * G_ * HE + he;
    float run = 0.f;
#pragma unroll
    for (int g = 0; g < G_; g++) {
        float t = p[(long long)g * HE];
        p[(long long)g * HE] = run;
        run += t;
    }
}

// ---------------- launch ----------------
extern "C" void kernel_launch(void* const* d_in, const int* in_sizes, int n_in,
                              void* d_out, int out_size)
{
    const float* x    = (const float*)d_in[0];
    const float* Wv   = (const float*)d_in[1];
    const float* bv   = (const float*)d_in[2];
    const float* Wg   = (const float*)d_in[3];
    const float* bg   = (const float*)d_in[4];
    const float* Win  = (const float*)d_in[5];
    const float* bin  = (const float*)d_in[6];
    const float* Wout = (const float*)d_in[7];
    const float* bout = (const float*)d_in[8];
    const float* gqq  = (const float*)d_in[9];
    const float* bqq  = (const float*)d_in[10];
    const float* gqk  = (const float*)d_in[11];
    const float* bqk  = (const float*)d_in[12];
    const float* glq  = (const float*)d_in[13];
    const float* blq  = (const float*)d_in[14];
    const float* glk  = (const float*)d_in[15];
    const float* blk  = (const float*)d_in[16];
    float* out = (float*)d_out;

    float *v_p, *gate_p, *vq_p, *om_p, *xh_p, *qq_p, *qk_p, *lq_p, *lk_p, *attn_p, *kv_p;
    cudaGetSymbolAddress((void**)&v_p,    g_v);
    cudaGetSymbolAddress((void**)&gate_p, g_gate);
    cudaGetSymbolAddress((void**)&vq_p,   g_vq);
    cudaGetSymbolAddress((void**)&om_p,   g_om);
    cudaGetSymbolAddress((void**)&xh_p,   g_xh);
    cudaGetSymbolAddress((void**)&qq_p,   g_qq);
    cudaGetSymbolAddress((void**)&qk_p,   g_qk);
    cudaGetSymbolAddress((void**)&lq_p,   g_lq);
    cudaGetSymbolAddress((void**)&lk_p,   g_lk);
    cudaGetSymbolAddress((void**)&attn_p, g_attn);
    cudaGetSymbolAddress((void**)&kv_p,   g_kv);

    dim3 tpb(256);

    // 1-3: projections with fused silu
    sgemm_k<false, EPI_SILU><<<dim3(INNER_/128, BS_/128), tpb>>>(
        x, Wv, v_p, BS_, INNER_, D_, 0, 0, 0, bv, nullptr, nullptr);
    sgemm_k<false, EPI_SILU><<<dim3(INNER_/128, BS_/128), tpb>>>(
        x, Wg, gate_p, BS_, INNER_, D_, 0, 0, 0, bg, nullptr, nullptr);
    sgemm_k<false, EPI_SILU><<<dim3(HEAD_/128, BS_/128), tpb>>>(
        x, Win, xh_p, BS_, HEAD_, D_, 0, 0, 0, bin, nullptr, nullptr);

    // 4: per-channel affine q/k
    affine_k<<<(BS_*HEAD_)/256, 256>>>(xh_p, gqq, bqq, gqk, bqk, glq, blq, glk, blk,
                                       qq_p, qk_p, lq_p, lk_p);

    // 5: masked relu^2 attention scores per chunk
    scores_k<<<dim3(GRP/64, GRP/64, NCHUNK), tpb>>>(qq_p, qk_p, attn_p);

    // 6: v_quad = attn @ v (batched over 64 chunks)
    sgemm_k<false, EPI_NONE><<<dim3(INNER_/128, GRP/128, NCHUNK), tpb>>>(
        attn_p, v_p, vq_p, GRP, INNER_, GRP,
        (long long)GRP*GRP, (long long)GRP*INNER_, (long long)GRP*INNER_,
        nullptr, nullptr, nullptr);

    // 7: kv = lin_k^T @ v per chunk
    sgemm_k<true, EPI_NONE><<<dim3(INNER_/128, HEAD_/128, NCHUNK), tpb>>>(
        lk_p, v_p, kv_p, HEAD_, INNER_, GRP,
        (long long)GRP*HEAD_, (long long)GRP*INNER_, (long long)HEAD_*INNER_,
        nullptr, nullptr, nullptr);

    // 8: exclusive cumsum over chunk axis
    cumsum_k<<<(B_*HEAD_*INNER_)/256, 256>>>(kv_p);

    // 9: o_mid = (lin_q @ kv_excl + v_quad) * gate
    sgemm_k<false, EPI_VQG><<<dim3(INNER_/128, GRP/128, NCHUNK), tpb>>>(
        lq_p, kv_p, om_p, GRP, INNER_, HEAD_,
        (long long)GRP*HEAD_, (long long)HEAD_*INNER_, (long long)GRP*INNER_,
        nullptr, vq_p, gate_p);

    // 10: out = o_mid @ Wout + bout
    sgemm_k<false, EPI_BIAS><<<dim3(D_/128, BS_/128), tpb>>>(
        om_p, Wout, out, BS_, D_, INNER_, 0, 0, 0, bout, nullptr, nullptr);
}

// round 6
// speedup vs baseline: 2.2575x; 2.2575x over previous
#include <cuda_runtime.h>
#include <cuda_bf16.h>
#include <math.h>
#include <stdint.h>

#define B_     4
#define S_     4096
#define D_     1024
#define GRP    256
#define HEAD_  128
#define INNER_ 2048
#define G_     16
#define NCHUNK (B_*G_)      // 64
#define BS_    (B_*S_)      // 16384

typedef __nv_bfloat16 bf16;

// ---------------- scratch (no cudaMalloc allowed) ----------------
// fp32 intermediates
__device__ float g_v    [(size_t)BS_*INNER_];
__device__ float g_gate [(size_t)BS_*INNER_];
__device__ float g_vq   [(size_t)BS_*INNER_];
__device__ float g_xh   [(size_t)BS_*HEAD_];
__device__ float g_qq   [(size_t)BS_*HEAD_];
__device__ float g_qk   [(size_t)BS_*HEAD_];
__device__ float g_lk   [(size_t)BS_*HEAD_];
__device__ float g_kvT  [(size_t)NCHUNK*HEAD_*INNER_];  // [chunk][e][h] pre-cumsum
// bf16 hi/lo split operands
__device__ bf16 g_xh16  [2][(size_t)BS_*D_];
__device__ bf16 g_wvT16 [2][(size_t)INNER_*D_];
__device__ bf16 g_wgT16 [2][(size_t)INNER_*D_];
__device__ bf16 g_winT16[2][(size_t)HEAD_*D_];
__device__ bf16 g_woutT16[2][(size_t)D_*INNER_];
__device__ bf16 g_attn16[2][(size_t)NCHUNK*GRP*GRP];
__device__ bf16 g_vT16  [2][(size_t)BS_*INNER_];
__device__ bf16 g_lkT16 [2][(size_t)BS_*HEAD_];
__device__ bf16 g_lq16  [2][(size_t)BS_*HEAD_];
__device__ bf16 g_kv16  [2][(size_t)NCHUNK*HEAD_*INNER_];
__device__ bf16 g_om16  [2][(size_t)BS_*INNER_];

// ---------------- helpers ----------------
__device__ __forceinline__ uint32_t smem_to_u32(const void* p) {
    uint32_t a;
    asm("{ .reg .u64 t; cvta.to.shared.u64 t, %1; cvt.u32.u64 %0, t; }" : "=r"(a) : "l"(p));
    return a;
}
__device__ __forceinline__ void cp_async16(uint32_t dst, const void* src) {
    asm volatile("cp.async.cg.shared.global [%0], [%1], 16;" :: "r"(dst), "l"(src));
}
#define CP_COMMIT() asm volatile("cp.async.commit_group;" ::: "memory")
#define CP_WAIT0()  asm volatile("cp.async.wait_group 0;" ::: "memory")
#define CP_WAIT1()  asm volatile("cp.async.wait_group 1;" ::: "memory")

__device__ __forceinline__ void mma_bf16(float (&d)[4], const uint32_t (&a)[4],
                                         const uint32_t b0, const uint32_t b1) {
    asm volatile(
        "mma.sync.aligned.m16n8k16.row.col.f32.bf16.bf16.f32 "
        "{%0,%1,%2,%3}, {%4,%5,%6,%7}, {%8,%9}, {%0,%1,%2,%3};"
        : "+f"(d[0]), "+f"(d[1]), "+f"(d[2]), "+f"(d[3])
        : "r"(a[0]), "r"(a[1]), "r"(a[2]), "r"(a[3]), "r"(b0), "r"(b1));
}
__device__ __forceinline__ void split2(float x, bf16& h, bf16& l) {
    h = __float2bfloat16(x);
    l = __float2bfloat16(x - __bfloat162float(h));
}

// ---------------- bf16x2-split GEMM: C = A @ Bt^T, 128x128x32 tile ----------------
// A,B given as (hi,lo) bf16 arrays, row-major [M,K]/[N,K].
#define EPI_NONE 0
#define EPI_SILU 1
#define EPI_BIAS 2
#define EPI_VQG  3
#define RW       20                     // 32-bit words per row (16 data + 4 pad): conflict-free
#define TILE_W   (128 * RW)             // 2560 words per split-tile
#define STAGE_W  (4 * TILE_W)           // Ah, Al, Bh, Bl
#define TG_SMEM  (2 * STAGE_W * 4)      // 81920 bytes

template<int EPI>
__global__ void __launch_bounds__(256, 2)
tgemm_k(const bf16* __restrict__ Ah, const bf16* __restrict__ Al,
        const bf16* __restrict__ Bh, const bf16* __restrict__ Bl,
        float* __restrict__ C, bf16* __restrict__ Ch, bf16* __restrict__ Cl,
        int M, int N, int K,
        long long sA, long long sB, long long sC,
        const float* __restrict__ bias,
        const float* __restrict__ add, const float* __restrict__ gate)
{
    extern __shared__ uint32_t smem[];
    const uint32_t smem_u32 = smem_to_u32(smem);

    const int tid  = threadIdx.x;
    const int wid  = tid >> 5, lane = tid & 31;
    const int wm   = wid & 3;            // 4 warp rows x 32
    const int wn   = wid >> 2;           // 2 warp cols x 64
    const int g    = lane >> 2;
    const int t4   = lane & 3;

    const long long bz = blockIdx.z;
    Ah += bz * sA;  Al += bz * sA;
    Bh += bz * sB;  Bl += bz * sB;
    const long long cb = bz * sC;

    const int row0 = blockIdx.y * 128;
    const int col0 = blockIdx.x * 128;

    const int lr  = tid >> 1;            // 0..127
    const int lwc = (tid & 1) * 8;       // word col 0 or 8

    float acc[2][8][4];
#pragma unroll
    for (int i = 0; i < 2; i++)
#pragma unroll
        for (int j = 0; j < 8; j++)
#pragma unroll
            for (int q = 0; q < 4; q++) acc[i][j][q] = 0.f;

    const int T = K >> 5;

    auto load_stage = [&](int t, int s) {
        const int kt = t * 32;
        const uint32_t base = smem_u32 + (uint32_t)(s * STAGE_W) * 4;
#pragma unroll
        for (int c = 0; c < 2; ++c) {
            const int wc = lwc + c * 4;
            const uint32_t off = (uint32_t)(lr * RW + wc) * 4;
            const long long ak = (long long)(row0 + lr) * K + kt + wc * 2;
            const long long bk = (long long)(col0 + lr) * K + kt + wc * 2;
            cp_async16(base + 0 * TILE_W * 4 + off, Ah + ak);
            cp_async16(base + 1 * TILE_W * 4 + off, Al + ak);
            cp_async16(base + 2 * TILE_W * 4 + off, Bh + bk);
            cp_async16(base + 3 * TILE_W * 4 + off, Bl + bk);
        }
        CP_COMMIT();
    };

    auto compute_stage = [&](int s) {
        const uint32_t* ah = smem + s * STAGE_W + (wm * 32) * RW;
        const uint32_t* al = ah + TILE_W;
        const uint32_t* bh = smem + s * STAGE_W + 2 * TILE_W + (wn * 64) * RW;
        const uint32_t* bl = bh + TILE_W;
#pragma unroll
        for (int ks = 0; ks < 2; ++ks) {
            const int c0 = ks * 8 + t4;
            uint32_t A_h[2][4], A_l[2][4];
#pragma unroll
            for (int i = 0; i < 2; ++i) {
                const uint32_t* p = ah + (i * 16 + g) * RW + c0;
                A_h[i][0] = p[0]; A_h[i][1] = p[8 * RW]; A_h[i][2] = p[4]; A_h[i][3] = p[8 * RW + 4];
                const uint32_t* q = al + (i * 16 + g) * RW + c0;
                A_l[i][0] = q[0]; A_l[i][1] = q[8 * RW]; A_l[i][2] = q[4]; A_l[i][3] = q[8 * RW + 4];
            }
#pragma unroll
            for (int j = 0; j < 8; ++j) {
                const uint32_t* p = bh + (j * 8 + g) * RW + c0;
                const uint32_t* q = bl + (j * 8 + g) * RW + c0;
                const uint32_t bh0 = p[0], bh1 = p[4];
                const uint32_t bl0 = q[0], bl1 = q[4];
#pragma unroll
                for (int i = 0; i < 2; ++i) {
                    mma_bf16(acc[i][j], A_h[i], bh0, bh1);
                    mma_bf16(acc[i][j], A_h[i], bl0, bl1);
                    mma_bf16(acc[i][j], A_l[i], bh0, bh1);
                }
            }
        }
    };

    load_stage(0, 0);
    for (int t = 0; t < T; ++t) {
        if (t + 1 < T) { load_stage(t + 1, (t + 1) & 1); CP_WAIT1(); }
        else          { CP_WAIT0(); }
        __syncthreads();
        compute_stage(t & 1);
        __syncthreads();
    }

    // -------- epilogue: registers -> gmem --------
    const float* addp  = (EPI == EPI_VQG) ? add  + cb : nullptr;
    const float* gatep = (EPI == EPI_VQG) ? gate + cb : nullptr;
#pragma unroll
    for (int i = 0; i < 2; ++i) {
        const int rbase = row0 + wm * 32 + i * 16 + g;
#pragma unroll
        for (int j = 0; j < 8; ++j) {
            const int c = col0 + wn * 64 + j * 8 + t4 * 2;
#pragma unroll
            for (int h = 0; h < 2; ++h) {
                const int rr = rbase + h * 8;
                const long long idx = (long long)rr * N + c;
                float v0 = acc[i][j][h * 2 + 0];
                float v1 = acc[i][j][h * 2 + 1];
                if (EPI == EPI_SILU) {
                    float u0 = v0 + bias[c],     u1 = v1 + bias[c + 1];
                    v0 = u0 / (1.f + expf(-u0)); v1 = u1 / (1.f + expf(-u1));
                    *(float2*)&C[cb + idx] = make_float2(v0, v1);
                } else if (EPI == EPI_BIAS) {
                    v0 += bias[c]; v1 += bias[c + 1];
                    *(float2*)&C[cb + idx] = make_float2(v0, v1);
                } else if (EPI == EPI_NONE) {
                    *(float2*)&C[cb + idx] = make_float2(v0, v1);
                } else { // EPI_VQG: (acc + vq) * gate  -> bf16 hi/lo
                    v0 = (v0 + addp[idx])     * gatep[idx];
                    v1 = (v1 + addp[idx + 1]) * gatep[idx + 1];
                    bf16 h0, l0, h1, l1;
                    split2(v0, h0, l0); split2(v1, h1, l1);
                    *(__nv_bfloat162*)&Ch[cb + idx] = __nv_bfloat162(h0, h1);
                    *(__nv_bfloat162*)&Cl[cb + idx] = __nv_bfloat162(l0, l1);
                }
            }
        }
    }
}

// ---------------- elementwise split: fp32 -> (hi, lo) bf16 ----------------
__global__ void split_k(const float* __restrict__ in, bf16* __restrict__ oh,
                        bf16* __restrict__ ol, long long n)
{
    long long i = (long long)blockIdx.x * blockDim.x + threadIdx.x;
    if (i >= n) return;
    bf16 h, l;
    split2(in[i], h, l);
    oh[i] = h; ol[i] = l;
}

// ---------------- batched transpose + split: in[R,C] fp32 -> outT[C,R] hi/lo ----------------
__global__ void transpose_split_k(const float* __restrict__ in,
                                  bf16* __restrict__ oh, bf16* __restrict__ ol,
                                  int R, int C, long long sIn, long long sOut)
{
    __shared__ float tile[32][33];
    const long long bz = blockIdx.z;
    in += bz * sIn; oh += bz * sOut; ol += bz * sOut;
    const int c0 = blockIdx.x * 32, r0 = blockIdx.y * 32;
    const int x = threadIdx.x, y = threadIdx.y;   // 32 x 8
#pragma unroll
    for (int i = 0; i < 32; i += 8)
        tile[y + i][x] = in[(long long)(r0 + y + i) * C + c0 + x];
    __syncthreads();
#pragma unroll
    for (int i = 0; i < 32; i += 8) {
        bf16 h, l;
        split2(tile[x][y + i], h, l);
        const long long o = (long long)(c0 + y + i) * R + r0 + x;
        oh[o] = h; ol[o] = l;
    }
}

// ---------------- per-channel affine; lq emitted split ----------------
__global__ void affine_k(const float* __restrict__ xh,
                         const float* __restrict__ gqq, const float* __restrict__ bqq,
                         const float* __restrict__ gqk, const float* __restrict__ bqk,
                         const float* __restrict__ glq, const float* __restrict__ blq,
                         const float* __restrict__ glk, const float* __restrict__ blk,
                         float* __restrict__ qq, float* __restrict__ qk,
                         bf16* __restrict__ lqh, bf16* __restrict__ lql,
                         float* __restrict__ lk)
{
    long long i = (long long)blockIdx.x * blockDim.x + threadIdx.x;
    if (i >= (long long)BS_ * HEAD_) return;
    int h = (int)(i & (HEAD_ - 1));
    float v = xh[i];
    qq[i] = fmaf(v, gqq[h], bqq[h]);
    qk[i] = fmaf(v, gqk[h], bqk[h]);
    float lq = fmaf(v, glq[h], blq[h]);
    bf16 hh, ll; split2(lq, hh, ll);
    lqh[i] = hh; lql[i] = ll;
    lk[i] = fmaf(v, glk[h], blk[h]);
}

// ---------------- local quadratic scores (fp32 SIMT), split output ----------------
__global__ void __launch_bounds__(256)
scores_k(const float* __restrict__ qq, const float* __restrict__ qk,
         bf16* __restrict__ ah, bf16* __restrict__ al)
{
    __shared__ float Qs[64][68];
    __shared__ float Ks[64][68];
    const int chunk = blockIdx.z;
    const int m0 = blockIdx.x * 64;
    const int n0 = blockIdx.y * 64;
    const float* q  = qq + (long long)chunk * GRP * HEAD_;
    const float* kp = qk + (long long)chunk * GRP * HEAD_;
    bf16* outh = ah + (long long)chunk * GRP * GRP;
    bf16* outl = al + (long long)chunk * GRP * GRP;

    const int tid = threadIdx.x;
    const int tx = tid & 15, ty = tid >> 4;

    float acc[4][4] = {};
    for (int kh = 0; kh < HEAD_; kh += 64) {
        for (int i = tid; i < 64 * 16; i += 256) {
            int r = i >> 4, c4 = (i & 15) * 4;
            *(float4*)&Qs[r][c4] = *(const float4*)&q [(long long)(n0 + r) * HEAD_ + kh + c4];
            *(float4*)&Ks[r][c4] = *(const float4*)&kp[(long long)(m0 + r) * HEAD_ + kh + c4];
        }
        __syncthreads();
#pragma unroll 8
        for (int k = 0; k < 64; k++) {
            float a[4], b[4];
#pragma unroll
            for (int i = 0; i < 4; i++) a[i] = Qs[ty * 4 + i][k];
#pragma unroll
            for (int j = 0; j < 4; j++) b[j] = Ks[tx * 4 + j][k];
#pragma unroll
            for (int i = 0; i < 4; i++)
#pragma unroll
                for (int j = 0; j < 4; j++) acc[i][j] = fmaf(a[i], b[j], acc[i][j]);
        }
        __syncthreads();
    }

    const float inv_scale = 1.0f / 45.25483399593904f;
#pragma unroll
    for (int i = 0; i < 4; i++) {
        int n = n0 + ty * 4 + i;
#pragma unroll
        for (int j = 0; j < 4; j++) {
            int m = m0 + tx * 4 + j;
            float s = (m <= n) ? acc[i][j] * inv_scale : 0.f;
            s = fmaxf(s, 0.f);
            s = s * s;
            bf16 h, l; split2(s, h, l);
            const long long o = (long long)n * GRP + m;
            outh[o] = h; outl[o] = l;
        }
    }
}

// ---------------- exclusive cumsum over chunk axis, split output ----------------
__global__ void cumsum_k(const float* __restrict__ kv,
                         bf16* __restrict__ kh, bf16* __restrict__ kl)
{
    const long long HE = (long long)HEAD_ * INNER_;
    long long i = (long long)blockIdx.x * blockDim.x + threadIdx.x;
    if (i >= (long long)B_ * HE) return;
    long long b  = i / HE;
    long long he = i - b * HE;
    const long long base = b * G_ * HE + he;
    float run = 0.f;
#pragma unroll
    for (int g = 0; g < G_; g++) {
        bf16 h, l; split2(run, h, l);
        kh[base + (long long)g * HE] = h;
        kl[base + (long long)g * HE] = l;
        run += kv[base + (long long)g * HE];
    }
}

// ---------------- launch ----------------
extern "C" void kernel_launch(void* const* d_in, const int* in_sizes, int n_in,
                              void* d_out, int out_size)
{
    const float* x    = (const float*)d_in[0];
    const float* Wv   = (const float*)d_in[1];
    const float* bv   = (const float*)d_in[2];
    const float* Wg   = (const float*)d_in[3];
    const float* bg   = (const float*)d_in[4];
    const float* Win  = (const float*)d_in[5];
    const float* bin  = (const float*)d_in[6];
    const float* Wout = (const float*)d_in[7];
    const float* bout = (const float*)d_in[8];
    const float* gqq  = (const float*)d_in[9];
    const float* bqq  = (const float*)d_in[10];
    const float* gqk  = (const float*)d_in[11];
    const float* bqk  = (const float*)d_in[12];
    const float* glq  = (const float*)d_in[13];
    const float* blq  = (const float*)d_in[14];
    const float* glk  = (const float*)d_in[15];
    const float* blk  = (const float*)d_in[16];
    float* out = (float*)d_out;

    float *v_p, *gate_p, *vq_p, *xh_p, *qq_p, *qk_p, *lk_p, *kvT_p;
    cudaGetSymbolAddress((void**)&v_p,    g_v);
    cudaGetSymbolAddress((void**)&gate_p, g_gate);
    cudaGetSymbolAddress((void**)&vq_p,   g_vq);
    cudaGetSymbolAddress((void**)&xh_p,   g_xh);
    cudaGetSymbolAddress((void**)&qq_p,   g_qq);
    cudaGetSymbolAddress((void**)&qk_p,   g_qk);
    cudaGetSymbolAddress((void**)&lk_p,   g_lk);
    cudaGetSymbolAddress((void**)&kvT_p,  g_kvT);

    bf16 *x16, *wv16, *wg16, *wi16, *wo16, *at16, *vT16, *lkT16, *lq16, *kv16, *om16;
    cudaGetSymbolAddress((void**)&x16,   g_xh16);
    cudaGetSymbolAddress((void**)&wv16,  g_wvT16);
    cudaGetSymbolAddress((void**)&wg16,  g_wgT16);
    cudaGetSymbolAddress((void**)&wi16,  g_winT16);
    cudaGetSymbolAddress((void**)&wo16,  g_woutT16);
    cudaGetSymbolAddress((void**)&at16,  g_attn16);
    cudaGetSymbolAddress((void**)&vT16,  g_vT16);
    cudaGetSymbolAddress((void**)&lkT16, g_lkT16);
    cudaGetSymbolAddress((void**)&lq16,  g_lq16);
    cudaGetSymbolAddress((void**)&kv16,  g_kv16);
    cudaGetSymbolAddress((void**)&om16,  g_om16);

    // hi/lo plane offsets
    const size_t P_X   = (size_t)BS_*D_;
    const size_t P_WV  = (size_t)INNER_*D_;
    const size_t P_WI  = (size_t)HEAD_*D_;
    const size_t P_WO  = (size_t)D_*INNER_;
    const size_t P_AT  = (size_t)NCHUNK*GRP*GRP;
    const size_t P_VT  = (size_t)BS_*INNER_;
    const size_t P_LKT = (size_t)BS_*HEAD_;
    const size_t P_KV  = (size_t)NCHUNK*HEAD_*INNER_;

    cudaFuncSetAttribute(tgemm_k<EPI_SILU>, cudaFuncAttributeMaxDynamicSharedMemorySize, TG_SMEM);
    cudaFuncSetAttribute(tgemm_k<EPI_NONE>, cudaFuncAttributeMaxDynamicSharedMemorySize, TG_SMEM);
    cudaFuncSetAttribute(tgemm_k<EPI_BIAS>, cudaFuncAttributeMaxDynamicSharedMemorySize, TG_SMEM);
    cudaFuncSetAttribute(tgemm_k<EPI_VQG>,  cudaFuncAttributeMaxDynamicSharedMemorySize, TG_SMEM);

    dim3 tt(32, 8);

    // operand preparation: split x; transpose+split weights
    split_k<<<(int)(((long long)BS_*D_ + 255) / 256), 256>>>(x, x16, x16 + P_X, (long long)BS_*D_);
    transpose_split_k<<<dim3(INNER_/32, D_/32), tt>>>(Wv,   wv16, wv16 + P_WV, D_,     INNER_, 0, 0);
    transpose_split_k<<<dim3(INNER_/32, D_/32), tt>>>(Wg,   wg16, wg16 + P_WV, D_,     INNER_, 0, 0);
    transpose_split_k<<<dim3(HEAD_/32,  D_/32), tt>>>(Win,  wi16, wi16 + P_WI, D_,     HEAD_,  0, 0);
    transpose_split_k<<<dim3(D_/32, INNER_/32), tt>>>(Wout, wo16, wo16 + P_WO, INNER_, D_,     0, 0);

    // projections
    tgemm_k<EPI_SILU><<<dim3(INNER_/128, BS_/128), 256, TG_SMEM>>>(
        x16, x16 + P_X, wv16, wv16 + P_WV, v_p, nullptr, nullptr,
        BS_, INNER_, D_, 0, 0, 0, bv, nullptr, nullptr);
    tgemm_k<EPI_SILU><<<dim3(INNER_/128, BS_/128), 256, TG_SMEM>>>(
        x16, x16 + P_X, wg16, wg16 + P_WV, gate_p, nullptr, nullptr,
        BS_, INNER_, D_, 0, 0, 0, bg, nullptr, nullptr);
    tgemm_k<EPI_SILU><<<dim3(HEAD_/128, BS_/128), 256, TG_SMEM>>>(
        x16, x16 + P_X, wi16, wi16 + P_WI, xh_p, nullptr, nullptr,
        BS_, HEAD_, D_, 0, 0, 0, bin, nullptr, nullptr);

    // affine q/k (lq split-fused)
    affine_k<<<(BS_*HEAD_)/256, 256>>>(xh_p, gqq, bqq, gqk, bqk, glq, blq, glk, blk,
                                       qq_p, qk_p, lq16, lq16 + P_LKT, lk_p);

    // quadratic scores -> split attn
    scores_k<<<dim3(GRP/64, GRP/64, NCHUNK), 256>>>(qq_p, qk_p, at16, at16 + P_AT);

    // per-chunk transposes with split
    transpose_split_k<<<dim3(INNER_/32, GRP/32, NCHUNK), tt>>>(
        v_p, vT16, vT16 + P_VT, GRP, INNER_, (long long)GRP*INNER_, (long long)GRP*INNER_);
    transpose_split_k<<<dim3(HEAD_/32, GRP/32, NCHUNK), tt>>>(
        lk_p, lkT16, lkT16 + P_LKT, GRP, HEAD_, (long long)GRP*HEAD_, (long long)GRP*HEAD_);

    // v_quad = attn @ vT^T
    tgemm_k<EPI_NONE><<<dim3(INNER_/128, GRP/128, NCHUNK), 256, TG_SMEM>>>(
        at16, at16 + P_AT, vT16, vT16 + P_VT, vq_p, nullptr, nullptr,
        GRP, INNER_, GRP,
        (long long)GRP*GRP, (long long)GRP*INNER_, (long long)GRP*INNER_,
        nullptr, nullptr, nullptr);

    // kvT[e,h] = vT @ lkT^T
    tgemm_k<EPI_NONE><<<dim3(HEAD_/128, INNER_/128, NCHUNK), 256, TG_SMEM>>>(
        vT16, vT16 + P_VT, lkT16, lkT16 + P_LKT, kvT_p, nullptr, nullptr,
        INNER_, HEAD_, GRP,
        (long long)GRP*INNER_, (long long)GRP*HEAD_, (long long)HEAD_*INNER_,
        nullptr, nullptr, nullptr);

    // exclusive cumsum over chunk axis -> split kv
    cumsum_k<<<(B_*HEAD_*INNER_)/256, 256>>>(kvT_p, kv16, kv16 + P_KV);

    // o_mid = (lq @ kv^T + v_quad) * gate -> split om
    tgemm_k<EPI_VQG><<<dim3(INNER_/128, GRP/128, NCHUNK), 256, TG_SMEM>>>(
        lq16, lq16 + P_LKT, kv16, kv16 + P_KV, nullptr, om16, om16 + P_VT,
        GRP, INNER_, HEAD_,
        (long long)GRP*HEAD_, (long long)HEAD_*INNER_, (long long)GRP*INNER_,
        nullptr, vq_p, gate_p);

    // out = om @ WoutT^T + bout
    tgemm_k<EPI_BIAS><<<dim3(D_/128, BS_/128), 256, TG_SMEM>>>(
        om16, om16 + P_VT, wo16, wo16 + P_WO, out, nullptr, nullptr,
        BS_, D_, INNER_, 0, 0, 0, bout, nullptr, nullptr);
}